// round 16
// baseline (speedup 1.0000x reference)
#include <cuda_runtime.h>
#include <math.h>

#define SBn 2
#define NVn 3
#define NRn 2048
#define NCn 1000
#define NSn 40
#define NGn 15
#define NKEEP (NSn - NGn)   // 25
#define HWn (256*256)
#define NTH 256
#define CH 4                // candidates per thread (4*256=1024 >= 1000)

// Non-contracted IEEE-RN ops (match XLA emission; selection-critical path)
#define FMUL __fmul_rn
#define FADD __fadd_rn
#define FSUB __fsub_rn
#define FDIV __fdiv_rn

// x/256 == x * 2^-8 bit-exactly (pow2 scaling; same RN of same real value)
#define INV256 0.00390625f

typedef unsigned long long u64;

__device__ __forceinline__ float dot3_rn(float a0, float a1, float a2,
                                         float b0, float b1, float b2) {
    return FADD(FADD(FMUL(a0, b0), FMUL(a1, b1)), FMUL(a2, b2));
}

__global__ __launch_bounds__(NTH, 5)
void nerf_dgs_kernel(
    const float* __restrict__ rays,
    const float* __restrict__ poses,
    const float* __restrict__ focal,
    const float* __restrict__ cprm,
    const float* __restrict__ depth_map,
    const float* __restrict__ std_map,
    const float* __restrict__ normal_map,
    const float* __restrict__ W1,
    const float* __restrict__ b1,
    const float* __restrict__ W2,
    const float* __restrict__ b2,
    const float* __restrict__ u_coarse,
    const float* __restrict__ g_noise,
    const float* __restrict__ u_fill,
    float* __restrict__ out)
{
    const int ray = blockIdx.x;
    const int s   = ray / NRn;
    const int tid = threadIdx.x;
    const int lane = tid & 31;
    const int warp = tid >> 5;

    __shared__ float shz[NCn];
    __shared__ float shpt[NCn];
    __shared__ u64   shcomp[NCn];        // compacted nonzero keys
    __shared__ int   shm_cnt;            // compacted count
    __shared__ float shwt[8];            // per-warp scan values
    __shared__ float shred[8][4];
    __shared__ float shbc[4];            // mean, sw, any, stdg
    __shared__ float sh_ray[8];
    __shared__ float shview[NVn][16];
    __shared__ float shvdir[NVn][3];
    __shared__ float shA[256];           // MLP: h_j = relu(A_j + z*B_j)
    __shared__ float shB[256];
    __shared__ float4 shW2[256];         // W2 rows staged as float4
    __shared__ float shz40[NSn];
    __shared__ float shtmp40[NSn];
    __shared__ float shalpha[NSn];
    __shared__ float shout[NSn][4];
    __shared__ float shw[NSn];

    if (tid == 0) shm_cnt = 0;
    if (tid < 8) sh_ray[tid] = rays[(size_t)ray * 8 + tid];
    __syncthreads();

    const float o0 = sh_ray[0], o1 = sh_ray[1], o2 = sh_ray[2];
    const float d0 = sh_ray[3], d1 = sh_ray[4], d2 = sh_ray[5];
    const float nearz = sh_ray[6], farz = sh_ray[7];

    if (tid < NVn) {
        const int v = tid;
        const float* P = poses + (size_t)(s * NVn + v) * 16;
        #pragma unroll
        for (int ii = 0; ii < 3; ii++) {
            #pragma unroll
            for (int jj = 0; jj < 3; jj++) shview[v][ii * 3 + jj] = P[ii * 4 + jj];
            shview[v][9 + ii] = P[ii * 4 + 3];
        }
        shview[v][12] = focal[(s * NVn + v) * 2 + 0];
        shview[v][13] = focal[(s * NVn + v) * 2 + 1];
        shview[v][14] = cprm[(s * NVn + v) * 2 + 0];
        shview[v][15] = cprm[(s * NVn + v) * 2 + 1];
        shvdir[v][0] = dot3_rn(shview[v][0], shview[v][1], shview[v][2], d0, d1, d2);
        shvdir[v][1] = dot3_rn(shview[v][3], shview[v][4], shview[v][5], d0, d1, d2);
        shvdir[v][2] = dot3_rn(shview[v][6], shview[v][7], shview[v][8], d0, d1, d2);
    }

    // MLP affine precompute: h_j(z) = relu(A_j + z*B_j)  (continuous path;
    // reassociation safe — feeds only composite, no discrete selection)
    {
        const int j = tid;
        float w0 = W1[j], w1 = W1[256 + j], w2 = W1[512 + j];
        float w3 = W1[768 + j], w4 = W1[1024 + j], w5 = W1[1280 + j];
        shA[j] = b1[j] + o0 * w0 + o1 * w1 + o2 * w2 + d0 * w3 + d1 * w4 + d2 * w5;
        shB[j] = d0 * w0 + d1 * w1 + d2 * w2;
        shW2[j] = reinterpret_cast<const float4*>(W2)[j];
    }
    __syncthreads();

    // ============ Phase 1: per-candidate likelihood ============
    const float stepc   = FDIV(1.0f, 1000.0f);
    const float deltals = FDIV(FSUB(1.0f, stepc), 999.0f);
    const float ss      = FDIV(FSUB(farz, nearz), 1000.0f);
    const float ssh     = FMUL(ss, 0.5f);
    const float SQ2     = __fsqrt_rn(2.0f);

    for (int i = tid; i < NCn; i += NTH) {
        float u  = u_coarse[(size_t)ray * NCn + i];
        float zs = FADD(FMUL((float)i, deltals), FMUL(u, stepc));
        float z  = FADD(FMUL(nearz, FSUB(1.0f, zs)), FMUL(farz, zs));
        float px0 = FADD(o0, FMUL(z, d0));
        float px1 = FADD(o1, FMUL(z, d1));
        float px2 = FADD(o2, FMUL(z, d2));
        float best = 0.0f;
        #pragma unroll
        for (int v = 0; v < NVn; v++) {
            const float* P = &shview[v][0];
            float xc = FADD(dot3_rn(P[0], P[1], P[2], px0, px1, px2), P[9]);
            float yc = FADD(dot3_rn(P[3], P[4], P[5], px0, px1, px2), P[10]);
            float zc = FADD(dot3_rn(P[6], P[7], P[8], px0, px1, px2), P[11]);
            float ui = FDIV(xc, zc);
            float vi = FDIV(yc, zc);
            float un = FSUB(FMUL(FMUL(FADD(FMUL(ui, P[12]), P[14]), INV256), 2.0f), 1.0f);
            float vn = FSUB(FMUL(FMUL(FADD(FMUL(vi, P[13]), P[15]), INV256), 2.0f), 1.0f);
            float pxf = rintf(FSUB(FMUL(FMUL(FADD(un, 1.0f), 0.5f), 256.0f), 0.5f));
            float pyf = rintf(FSUB(FMUL(FMUL(FADD(vn, 1.0f), 0.5f), 256.0f), 0.5f));
            pxf = fminf(fmaxf(pxf, 0.0f), 255.0f);
            pyf = fminf(fmaxf(pyf, 0.0f), 255.0f);
            int lin = (int)pyf * 256 + (int)pxf;
            int mbase = (s * NVn + v) * HWn;
            float dref = depth_map[mbase + lin];
            float stdv = std_map[mbase + lin];
            if ((stdv != 0.0f) && (fabsf(FSUB(dref, zc)) < 0.05f)) {
                int nbase = (s * NVn + v) * 3 * HWn;
                float n0 = normal_map[nbase + lin];
                float n1 = normal_map[nbase + HWn + lin];
                float n2 = normal_map[nbase + 2 * HWn + lin];
                float cosd = dot3_rn(shvdir[v][0], shvdir[v][1], shvdir[v][2], n0, n1, n2);
                if (cosd <= 0.0f) {
                    float inv = FDIV(1.0f, FMUL(stdv, SQ2));
                    float a1 = FMUL(FSUB(FADD(zc, ssh), dref), inv);
                    float a2 = FMUL(FSUB(FSUB(zc, ssh), dref), inv);
                    float lik = FMUL(0.5f, fabsf(FSUB(erff(a1), erff(a2))));
                    best = fmaxf(best, lik);
                }
            }
        }
        shz[i]  = z;
        shpt[i] = best;
    }
    __syncthreads();

    // ============ Compact nonzero keys (set semantics; order irrelevant) ============
    #pragma unroll
    for (int q = 0; q < CH; q++) {
        int i = tid + q * NTH;
        bool nz = (i < NCn) && (shpt[i] > 0.0f);
        unsigned mask = __ballot_sync(0xFFFFFFFFu, nz);
        if (mask) {
            int leader = __ffs(mask) - 1;
            int base = 0;
            if (lane == leader) base = atomicAdd(&shm_cnt, __popc(mask));
            base = __shfl_sync(0xFFFFFFFFu, base, leader);
            if (nz) {
                int pos = base + __popc(mask & ((1u << lane) - 1u));
                shcomp[pos] = ((u64)__float_as_uint(shpt[i]) << 32) |
                              (u64)(0xFFFFFFFFu - (unsigned)i);
            }
        }
    }

    // ============ Phase 2: exclusive cumprod via shuffle scan + stats ============
    const int base_i = tid * CH;
    float myp[CH], myop[CH];
    float locprod = 1.0f;
    #pragma unroll
    for (int q = 0; q < CH; q++) {
        int i = base_i + q;
        float p = (i < NCn) ? shpt[i] : 0.0f;
        myp[q] = p;
        locprod *= (1.0f - p);
    }
    // warp-inclusive product scan (5 shfl steps)
    float incl = locprod;
    #pragma unroll
    for (int off = 1; off < 32; off <<= 1) {
        float o = __shfl_up_sync(0xFFFFFFFFu, incl, off);
        if (lane >= off) incl *= o;
    }
    if (lane == 31) shwt[warp] = incl;   // warp total
    __syncthreads();
    if (warp == 0) {
        float t = (lane < 8) ? shwt[lane] : 1.0f;
        float ip = t;
        #pragma unroll
        for (int off = 1; off < 8; off <<= 1) {
            float o = __shfl_up_sync(0xFFFFFFFFu, ip, off);
            if (lane >= off) ip *= o;
        }
        float ex = __shfl_up_sync(0xFFFFFFFFu, ip, 1);  // exclusive = inclusive[w-1]
        if (lane == 0) ex = 1.0f;
        if (lane < 8) shwt[lane] = ex;
    }
    __syncthreads();
    float excl_t = __shfl_up_sync(0xFFFFFFFFu, incl, 1);
    if (lane == 0) excl_t = 1.0f;
    float run = shwt[warp] * excl_t;

    float wsum_l = 0.0f, zw_l = 0.0f, any_l = 0.0f;
    #pragma unroll
    for (int q = 0; q < CH; q++) {
        int i = base_i + q;
        if (i < NCn) {
            float op = myp[q] * run;
            run *= (1.0f - myp[q]);
            myop[q] = op;
            wsum_l += op;
            zw_l += shz[i] * op;
            if (op != 0.0f) any_l = 1.0f;
        } else {
            myop[q] = 0.0f;
        }
    }
    #pragma unroll
    for (int off = 16; off > 0; off >>= 1) {
        wsum_l += __shfl_down_sync(0xFFFFFFFFu, wsum_l, off);
        zw_l   += __shfl_down_sync(0xFFFFFFFFu, zw_l, off);
        any_l   = fmaxf(any_l, __shfl_down_sync(0xFFFFFFFFu, any_l, off));
    }
    if (lane == 0) { shred[warp][0] = wsum_l; shred[warp][1] = zw_l; shred[warp][2] = any_l; }
    __syncthreads();
    if (tid == 0) {
        float ws = 0.0f, zw = 0.0f, an = 0.0f;
        #pragma unroll
        for (int w = 0; w < 8; w++) { ws += shred[w][0]; zw += shred[w][1]; an = fmaxf(an, shred[w][2]); }
        float sw = (ws > 0.0f) ? ws : 1.0f;
        shbc[0] = zw / sw; shbc[1] = sw; shbc[2] = an;
    }
    __syncthreads();
    const float mean = shbc[0];
    float var_l = 0.0f;
    #pragma unroll
    for (int q = 0; q < CH; q++) {
        int i = base_i + q;
        if (i < NCn) { float dz = shz[i] - mean; var_l += myop[q] * dz * dz; }
    }
    #pragma unroll
    for (int off = 16; off > 0; off >>= 1)
        var_l += __shfl_down_sync(0xFFFFFFFFu, var_l, off);
    if (lane == 0) shred[warp][3] = var_l;
    __syncthreads();
    if (tid == 0) {
        float var = 0.0f;
        #pragma unroll
        for (int w = 0; w < 8; w++) var += shred[w][3];
        shbc[3] = sqrtf(var / shbc[1]);
    }
    __syncthreads();

    // ============ Phase 3: zero-init + gauss fill, then parallel rank-select ============
    if (tid < NKEEP) {
        shz40[tid] = 0.0f;
    } else if (tid >= 32 && tid < 32 + NGn) {
        int gi = tid - 32;
        float g = g_noise[(size_t)ray * NGn + gi];
        bool ray_mask = (shbc[2] > 0.0f);
        shz40[NKEEP + gi] = ray_mask ? (g * shbc[3] + mean) : 0.0f;
    }
    __syncthreads();
    {
        const int m = shm_cnt;
        for (int t = tid; t < m; t += NTH) {
            u64 key = shcomp[t];
            int rank = 0;
            for (int j = 0; j < m; j++)
                rank += (shcomp[j] > key) ? 1 : 0;
            if (rank < NKEEP) {
                unsigned idx = 0xFFFFFFFFu - (unsigned)(key & 0xFFFFFFFFull);
                shz40[rank] = shz[idx];
            }
        }
    }
    __syncthreads();

    // ============ Phase 4: rank-sort, miss-fill, rank-sort ============
    if (tid < NSn) {
        float v = shz40[tid];
        int rank = 0;
        #pragma unroll
        for (int j = 0; j < NSn; j++) {
            float zj = shz40[j];
            rank += (zj < v || (zj == v && j < tid)) ? 1 : 0;
        }
        shtmp40[rank] = v;
    }
    __syncthreads();
    if (tid < NSn) {
        int nmiss = 0;
        #pragma unroll
        for (int j = 0; j < NSn; j++) nmiss += (shtmp40[j] == 0.0f) ? 1 : 0;
        float v = shtmp40[tid];
        if (v == 0.0f) {
            int nm = (nmiss > 1) ? nmiss : 1;
            float stepf = FDIV(FSUB(farz, nearz), (float)nm);
            float uf = u_fill[(size_t)ray * NSn + tid];
            v = FADD(FADD(nearz, FMUL((float)tid, stepf)), FMUL(uf, stepf));
        }
        shalpha[tid] = v;  // temp hold (pre-sort values)
    }
    __syncthreads();
    if (tid < NSn) {
        float v = shalpha[tid];
        int rank = 0;
        #pragma unroll
        for (int j = 0; j < NSn; j++) {
            float zj = shalpha[j];
            rank += (zj < v || (zj == v && j < tid)) ? 1 : 0;
        }
        shz40[rank] = v;
    }
    __syncthreads();

    // ============ Phase 5: MLP via affine form (warp per 5 samples) ============
    {
        const int s0 = warp * 5;
        for (int si = 0; si < 5; si++) {
            int sidx = s0 + si;
            float z = shz40[sidx];
            float a0 = 0.0f, a1 = 0.0f, a2 = 0.0f, a3 = 0.0f;
            #pragma unroll
            for (int q = 0; q < 8; q++) {
                int j = lane + 32 * q;
                float h = fmaxf(fmaf(z, shB[j], shA[j]), 0.0f);
                float4 w2 = shW2[j];
                a0 = fmaf(h, w2.x, a0);
                a1 = fmaf(h, w2.y, a1);
                a2 = fmaf(h, w2.z, a2);
                a3 = fmaf(h, w2.w, a3);
            }
            #pragma unroll
            for (int off = 16; off > 0; off >>= 1) {
                a0 += __shfl_down_sync(0xFFFFFFFFu, a0, off);
                a1 += __shfl_down_sync(0xFFFFFFFFu, a1, off);
                a2 += __shfl_down_sync(0xFFFFFFFFu, a2, off);
                a3 += __shfl_down_sync(0xFFFFFFFFu, a3, off);
            }
            if (lane == 0) {
                shout[sidx][0] = a0 + b2[0];
                shout[sidx][1] = a1 + b2[1];
                shout[sidx][2] = a2 + b2[2];
                shout[sidx][3] = a3 + b2[3];
            }
        }
    }
    __syncthreads();

    // ============ Phase 6: composite ============
    if (tid < NSn) {
        float z = shz40[tid];
        float delta = (tid < NSn - 1) ? (shz40[tid + 1] - z) : (farz - z);
        float sig = fmaxf(shout[tid][3], 0.0f);
        shalpha[tid] = 1.0f - expf(-delta * sig);
    }
    __syncthreads();
    const size_t WOFF = (size_t)SBn * NRn * NSn;
    const size_t ROFF = WOFF + (size_t)SBn * NRn * 3;
    if (tid == 0) {
        float T = 1.0f;
        float rgb0 = 0.0f, rgb1 = 0.0f, rgb2 = 0.0f, dep = 0.0f, sumw = 0.0f;
        #pragma unroll 8
        for (int i = 0; i < NSn; i++) {
            float a = shalpha[i];
            float w = a * T;
            T *= (1.0f - a + 1e-10f);
            shw[i] = w;
            rgb0 += w * shout[i][0];
            rgb1 += w * shout[i][1];
            rgb2 += w * shout[i][2];
            dep  += w * shz40[i];
            sumw += w;
        }
        float add = 1.0f - sumw;
        out[WOFF + (size_t)ray * 3 + 0] = rgb0 + add;
        out[WOFF + (size_t)ray * 3 + 1] = rgb1 + add;
        out[WOFF + (size_t)ray * 3 + 2] = rgb2 + add;
        out[ROFF + (size_t)ray] = dep;
    }
    __syncthreads();
    if (tid < NSn) out[(size_t)ray * NSn + tid] = shw[tid];
}

extern "C" void kernel_launch(void* const* d_in, const int* in_sizes, int n_in,
                              void* d_out, int out_size) {
    (void)in_sizes; (void)n_in; (void)out_size;
    nerf_dgs_kernel<<<SBn * NRn, NTH>>>(
        (const float*)d_in[0],  (const float*)d_in[1],  (const float*)d_in[2],
        (const float*)d_in[3],  (const float*)d_in[4],  (const float*)d_in[5],
        (const float*)d_in[6],  (const float*)d_in[7],  (const float*)d_in[8],
        (const float*)d_in[9],  (const float*)d_in[10], (const float*)d_in[11],
        (const float*)d_in[12], (const float*)d_in[13],
        (float*)d_out);
}

// round 17
// speedup vs baseline: 1.0881x; 1.0881x over previous
#include <cuda_runtime.h>
#include <math.h>

#define SBn 2
#define NVn 3
#define NRn 2048
#define NCn 1000
#define NSn 40
#define NGn 15
#define NKEEP (NSn - NGn)   // 25
#define HWn (256*256)
#define NTH 256
#define CH 4                // candidates per thread (4*256=1024 >= 1000)

// Non-contracted IEEE-RN ops (match XLA emission; selection-critical path)
#define FMUL __fmul_rn
#define FADD __fadd_rn
#define FSUB __fsub_rn
#define FDIV __fdiv_rn

// x/256 == x * 2^-8 bit-exactly (pow2 scaling; same RN of same real value)
#define INV256 0.00390625f

typedef unsigned long long u64;

__device__ __forceinline__ float dot3_rn(float a0, float a1, float a2,
                                         float b0, float b1, float b2) {
    return FADD(FADD(FMUL(a0, b0), FMUL(a1, b1)), FMUL(a2, b2));
}

__global__ __launch_bounds__(NTH, 4)
void nerf_dgs_kernel(
    const float* __restrict__ rays,
    const float* __restrict__ poses,
    const float* __restrict__ focal,
    const float* __restrict__ cprm,
    const float* __restrict__ depth_map,
    const float* __restrict__ std_map,
    const float* __restrict__ normal_map,
    const float* __restrict__ W1,
    const float* __restrict__ b1,
    const float* __restrict__ W2,
    const float* __restrict__ b2,
    const float* __restrict__ u_coarse,
    const float* __restrict__ g_noise,
    const float* __restrict__ u_fill,
    float* __restrict__ out)
{
    const int ray = blockIdx.x;
    const int s   = ray / NRn;
    const int tid = threadIdx.x;
    const int lane = tid & 31;
    const int warp = tid >> 5;

    __shared__ float shz[NCn];
    __shared__ float shpt[NCn];
    __shared__ u64   shcomp[NCn];        // compacted nonzero keys
    __shared__ int   shm_cnt;            // compacted count
    __shared__ float shwt[8];            // per-warp scan values
    __shared__ float shred[8][4];
    __shared__ float shbc[4];            // mean, sw, any, stdg
    __shared__ float sh_ray[8];
    __shared__ float shview[NVn][16];
    __shared__ float shvdir[NVn][3];
    __shared__ float shA[256];           // MLP: h_j = relu(A_j + z*B_j)
    __shared__ float shB[256];
    __shared__ float4 shW2[256];         // W2 rows staged as float4
    __shared__ float shz40[NSn];
    __shared__ float shtmp40[NSn];
    __shared__ float shalpha[NSn];
    __shared__ float shout[NSn][4];
    __shared__ float shw[NSn];

    if (tid == 0) shm_cnt = 0;
    if (tid < 8) sh_ray[tid] = rays[(size_t)ray * 8 + tid];
    __syncthreads();

    const float o0 = sh_ray[0], o1 = sh_ray[1], o2 = sh_ray[2];
    const float d0 = sh_ray[3], d1 = sh_ray[4], d2 = sh_ray[5];
    const float nearz = sh_ray[6], farz = sh_ray[7];

    if (tid < NVn) {
        const int v = tid;
        const float* P = poses + (size_t)(s * NVn + v) * 16;
        #pragma unroll
        for (int ii = 0; ii < 3; ii++) {
            #pragma unroll
            for (int jj = 0; jj < 3; jj++) shview[v][ii * 3 + jj] = P[ii * 4 + jj];
            shview[v][9 + ii] = P[ii * 4 + 3];
        }
        shview[v][12] = focal[(s * NVn + v) * 2 + 0];
        shview[v][13] = focal[(s * NVn + v) * 2 + 1];
        shview[v][14] = cprm[(s * NVn + v) * 2 + 0];
        shview[v][15] = cprm[(s * NVn + v) * 2 + 1];
        shvdir[v][0] = dot3_rn(shview[v][0], shview[v][1], shview[v][2], d0, d1, d2);
        shvdir[v][1] = dot3_rn(shview[v][3], shview[v][4], shview[v][5], d0, d1, d2);
        shvdir[v][2] = dot3_rn(shview[v][6], shview[v][7], shview[v][8], d0, d1, d2);
    }

    // MLP affine precompute: h_j(z) = relu(A_j + z*B_j)  (continuous path;
    // reassociation safe — feeds only composite, no discrete selection)
    {
        const int j = tid;
        float w0 = W1[j], w1 = W1[256 + j], w2 = W1[512 + j];
        float w3 = W1[768 + j], w4 = W1[1024 + j], w5 = W1[1280 + j];
        shA[j] = b1[j] + o0 * w0 + o1 * w1 + o2 * w2 + d0 * w3 + d1 * w4 + d2 * w5;
        shB[j] = d0 * w0 + d1 * w1 + d2 * w2;
        shW2[j] = reinterpret_cast<const float4*>(W2)[j];
    }
    __syncthreads();

    // ============ Phase 1: per-candidate likelihood ============
    const float stepc   = FDIV(1.0f, 1000.0f);
    const float deltals = FDIV(FSUB(1.0f, stepc), 999.0f);
    const float ss      = FDIV(FSUB(farz, nearz), 1000.0f);
    const float ssh     = FMUL(ss, 0.5f);
    const float SQ2     = __fsqrt_rn(2.0f);

    for (int i = tid; i < NCn; i += NTH) {
        float u  = u_coarse[(size_t)ray * NCn + i];
        float zs = FADD(FMUL((float)i, deltals), FMUL(u, stepc));
        float z  = FADD(FMUL(nearz, FSUB(1.0f, zs)), FMUL(farz, zs));
        float px0 = FADD(o0, FMUL(z, d0));
        float px1 = FADD(o1, FMUL(z, d1));
        float px2 = FADD(o2, FMUL(z, d2));
        float best = 0.0f;
        #pragma unroll
        for (int v = 0; v < NVn; v++) {
            const float* P = &shview[v][0];
            float xc = FADD(dot3_rn(P[0], P[1], P[2], px0, px1, px2), P[9]);
            float yc = FADD(dot3_rn(P[3], P[4], P[5], px0, px1, px2), P[10]);
            float zc = FADD(dot3_rn(P[6], P[7], P[8], px0, px1, px2), P[11]);
            float ui = FDIV(xc, zc);
            float vi = FDIV(yc, zc);
            float un = FSUB(FMUL(FMUL(FADD(FMUL(ui, P[12]), P[14]), INV256), 2.0f), 1.0f);
            float vn = FSUB(FMUL(FMUL(FADD(FMUL(vi, P[13]), P[15]), INV256), 2.0f), 1.0f);
            float pxf = rintf(FSUB(FMUL(FMUL(FADD(un, 1.0f), 0.5f), 256.0f), 0.5f));
            float pyf = rintf(FSUB(FMUL(FMUL(FADD(vn, 1.0f), 0.5f), 256.0f), 0.5f));
            pxf = fminf(fmaxf(pxf, 0.0f), 255.0f);
            pyf = fminf(fmaxf(pyf, 0.0f), 255.0f);
            int lin = (int)pyf * 256 + (int)pxf;
            int mbase = (s * NVn + v) * HWn;
            float dref = depth_map[mbase + lin];
            float stdv = std_map[mbase + lin];
            if ((stdv != 0.0f) && (fabsf(FSUB(dref, zc)) < 0.05f)) {
                int nbase = (s * NVn + v) * 3 * HWn;
                float n0 = normal_map[nbase + lin];
                float n1 = normal_map[nbase + HWn + lin];
                float n2 = normal_map[nbase + 2 * HWn + lin];
                float cosd = dot3_rn(shvdir[v][0], shvdir[v][1], shvdir[v][2], n0, n1, n2);
                if (cosd <= 0.0f) {
                    float inv = FDIV(1.0f, FMUL(stdv, SQ2));
                    float a1 = FMUL(FSUB(FADD(zc, ssh), dref), inv);
                    float a2 = FMUL(FSUB(FSUB(zc, ssh), dref), inv);
                    float lik = FMUL(0.5f, fabsf(FSUB(erff(a1), erff(a2))));
                    best = fmaxf(best, lik);
                }
            }
        }
        shz[i]  = z;
        shpt[i] = best;
    }
    __syncthreads();

    // ============ Compact nonzero keys (set semantics; order irrelevant) ============
    #pragma unroll
    for (int q = 0; q < CH; q++) {
        int i = tid + q * NTH;
        bool nz = (i < NCn) && (shpt[i] > 0.0f);
        unsigned mask = __ballot_sync(0xFFFFFFFFu, nz);
        if (mask) {
            int leader = __ffs(mask) - 1;
            int base = 0;
            if (lane == leader) base = atomicAdd(&shm_cnt, __popc(mask));
            base = __shfl_sync(0xFFFFFFFFu, base, leader);
            if (nz) {
                int pos = base + __popc(mask & ((1u << lane) - 1u));
                shcomp[pos] = ((u64)__float_as_uint(shpt[i]) << 32) |
                              (u64)(0xFFFFFFFFu - (unsigned)i);
            }
        }
    }

    // ============ Phase 2: exclusive cumprod via shuffle scan + stats ============
    const int base_i = tid * CH;
    float myp[CH], myop[CH];
    float locprod = 1.0f;
    #pragma unroll
    for (int q = 0; q < CH; q++) {
        int i = base_i + q;
        float p = (i < NCn) ? shpt[i] : 0.0f;
        myp[q] = p;
        locprod *= (1.0f - p);
    }
    // warp-inclusive product scan (5 shfl steps)
    float incl = locprod;
    #pragma unroll
    for (int off = 1; off < 32; off <<= 1) {
        float o = __shfl_up_sync(0xFFFFFFFFu, incl, off);
        if (lane >= off) incl *= o;
    }
    if (lane == 31) shwt[warp] = incl;   // warp total
    __syncthreads();
    if (warp == 0) {
        float t = (lane < 8) ? shwt[lane] : 1.0f;
        float ip = t;
        #pragma unroll
        for (int off = 1; off < 8; off <<= 1) {
            float o = __shfl_up_sync(0xFFFFFFFFu, ip, off);
            if (lane >= off) ip *= o;
        }
        float ex = __shfl_up_sync(0xFFFFFFFFu, ip, 1);  // exclusive = inclusive[w-1]
        if (lane == 0) ex = 1.0f;
        if (lane < 8) shwt[lane] = ex;
    }
    __syncthreads();
    float excl_t = __shfl_up_sync(0xFFFFFFFFu, incl, 1);
    if (lane == 0) excl_t = 1.0f;
    float run = shwt[warp] * excl_t;

    float wsum_l = 0.0f, zw_l = 0.0f, any_l = 0.0f;
    #pragma unroll
    for (int q = 0; q < CH; q++) {
        int i = base_i + q;
        if (i < NCn) {
            float op = myp[q] * run;
            run *= (1.0f - myp[q]);
            myop[q] = op;
            wsum_l += op;
            zw_l += shz[i] * op;
            if (op != 0.0f) any_l = 1.0f;
        } else {
            myop[q] = 0.0f;
        }
    }
    #pragma unroll
    for (int off = 16; off > 0; off >>= 1) {
        wsum_l += __shfl_down_sync(0xFFFFFFFFu, wsum_l, off);
        zw_l   += __shfl_down_sync(0xFFFFFFFFu, zw_l, off);
        any_l   = fmaxf(any_l, __shfl_down_sync(0xFFFFFFFFu, any_l, off));
    }
    if (lane == 0) { shred[warp][0] = wsum_l; shred[warp][1] = zw_l; shred[warp][2] = any_l; }
    __syncthreads();
    if (tid == 0) {
        float ws = 0.0f, zw = 0.0f, an = 0.0f;
        #pragma unroll
        for (int w = 0; w < 8; w++) { ws += shred[w][0]; zw += shred[w][1]; an = fmaxf(an, shred[w][2]); }
        float sw = (ws > 0.0f) ? ws : 1.0f;
        shbc[0] = zw / sw; shbc[1] = sw; shbc[2] = an;
    }
    __syncthreads();
    const float mean = shbc[0];
    float var_l = 0.0f;
    #pragma unroll
    for (int q = 0; q < CH; q++) {
        int i = base_i + q;
        if (i < NCn) { float dz = shz[i] - mean; var_l += myop[q] * dz * dz; }
    }
    #pragma unroll
    for (int off = 16; off > 0; off >>= 1)
        var_l += __shfl_down_sync(0xFFFFFFFFu, var_l, off);
    if (lane == 0) shred[warp][3] = var_l;
    __syncthreads();
    if (tid == 0) {
        float var = 0.0f;
        #pragma unroll
        for (int w = 0; w < 8; w++) var += shred[w][3];
        shbc[3] = sqrtf(var / shbc[1]);
    }
    __syncthreads();

    // ============ Phase 3: zero-init + gauss fill, then parallel rank-select ============
    if (tid < NKEEP) {
        shz40[tid] = 0.0f;
    } else if (tid >= 32 && tid < 32 + NGn) {
        int gi = tid - 32;
        float g = g_noise[(size_t)ray * NGn + gi];
        bool ray_mask = (shbc[2] > 0.0f);
        shz40[NKEEP + gi] = ray_mask ? (g * shbc[3] + mean) : 0.0f;
    }
    __syncthreads();
    {
        const int m = shm_cnt;
        for (int t = tid; t < m; t += NTH) {
            u64 key = shcomp[t];
            int rank = 0;
            for (int j = 0; j < m; j++)
                rank += (shcomp[j] > key) ? 1 : 0;
            if (rank < NKEEP) {
                unsigned idx = 0xFFFFFFFFu - (unsigned)(key & 0xFFFFFFFFull);
                shz40[rank] = shz[idx];
            }
        }
    }
    __syncthreads();

    // ============ Phase 4: rank-sort, miss-fill, rank-sort ============
    if (tid < NSn) {
        float v = shz40[tid];
        int rank = 0;
        #pragma unroll
        for (int j = 0; j < NSn; j++) {
            float zj = shz40[j];
            rank += (zj < v || (zj == v && j < tid)) ? 1 : 0;
        }
        shtmp40[rank] = v;
    }
    __syncthreads();
    if (tid < NSn) {
        int nmiss = 0;
        #pragma unroll
        for (int j = 0; j < NSn; j++) nmiss += (shtmp40[j] == 0.0f) ? 1 : 0;
        float v = shtmp40[tid];
        if (v == 0.0f) {
            int nm = (nmiss > 1) ? nmiss : 1;
            float stepf = FDIV(FSUB(farz, nearz), (float)nm);
            float uf = u_fill[(size_t)ray * NSn + tid];
            v = FADD(FADD(nearz, FMUL((float)tid, stepf)), FMUL(uf, stepf));
        }
        shalpha[tid] = v;  // temp hold (pre-sort values)
    }
    __syncthreads();
    if (tid < NSn) {
        float v = shalpha[tid];
        int rank = 0;
        #pragma unroll
        for (int j = 0; j < NSn; j++) {
            float zj = shalpha[j];
            rank += (zj < v || (zj == v && j < tid)) ? 1 : 0;
        }
        shz40[rank] = v;
    }
    __syncthreads();

    // ============ Phase 5: MLP via affine form (warp per 5 samples) ============
    {
        const int s0 = warp * 5;
        for (int si = 0; si < 5; si++) {
            int sidx = s0 + si;
            float z = shz40[sidx];
            float a0 = 0.0f, a1 = 0.0f, a2 = 0.0f, a3 = 0.0f;
            #pragma unroll
            for (int q = 0; q < 8; q++) {
                int j = lane + 32 * q;
                float h = fmaxf(fmaf(z, shB[j], shA[j]), 0.0f);
                float4 w2 = shW2[j];
                a0 = fmaf(h, w2.x, a0);
                a1 = fmaf(h, w2.y, a1);
                a2 = fmaf(h, w2.z, a2);
                a3 = fmaf(h, w2.w, a3);
            }
            #pragma unroll
            for (int off = 16; off > 0; off >>= 1) {
                a0 += __shfl_down_sync(0xFFFFFFFFu, a0, off);
                a1 += __shfl_down_sync(0xFFFFFFFFu, a1, off);
                a2 += __shfl_down_sync(0xFFFFFFFFu, a2, off);
                a3 += __shfl_down_sync(0xFFFFFFFFu, a3, off);
            }
            if (lane == 0) {
                shout[sidx][0] = a0 + b2[0];
                shout[sidx][1] = a1 + b2[1];
                shout[sidx][2] = a2 + b2[2];
                shout[sidx][3] = a3 + b2[3];
            }
        }
    }
    __syncthreads();

    // ============ Phase 6: composite ============
    if (tid < NSn) {
        float z = shz40[tid];
        float delta = (tid < NSn - 1) ? (shz40[tid + 1] - z) : (farz - z);
        float sig = fmaxf(shout[tid][3], 0.0f);
        shalpha[tid] = 1.0f - expf(-delta * sig);
    }
    __syncthreads();
    const size_t WOFF = (size_t)SBn * NRn * NSn;
    const size_t ROFF = WOFF + (size_t)SBn * NRn * 3;
    if (tid == 0) {
        float T = 1.0f;
        float rgb0 = 0.0f, rgb1 = 0.0f, rgb2 = 0.0f, dep = 0.0f, sumw = 0.0f;
        #pragma unroll 8
        for (int i = 0; i < NSn; i++) {
            float a = shalpha[i];
            float w = a * T;
            T *= (1.0f - a + 1e-10f);
            shw[i] = w;
            rgb0 += w * shout[i][0];
            rgb1 += w * shout[i][1];
            rgb2 += w * shout[i][2];
            dep  += w * shz40[i];
            sumw += w;
        }
        float add = 1.0f - sumw;
        out[WOFF + (size_t)ray * 3 + 0] = rgb0 + add;
        out[WOFF + (size_t)ray * 3 + 1] = rgb1 + add;
        out[WOFF + (size_t)ray * 3 + 2] = rgb2 + add;
        out[ROFF + (size_t)ray] = dep;
    }
    __syncthreads();
    if (tid < NSn) out[(size_t)ray * NSn + tid] = shw[tid];
}

extern "C" void kernel_launch(void* const* d_in, const int* in_sizes, int n_in,
                              void* d_out, int out_size) {
    (void)in_sizes; (void)n_in; (void)out_size;
    nerf_dgs_kernel<<<SBn * NRn, NTH>>>(
        (const float*)d_in[0],  (const float*)d_in[1],  (const float*)d_in[2],
        (const float*)d_in[3],  (const float*)d_in[4],  (const float*)d_in[5],
        (const float*)d_in[6],  (const float*)d_in[7],  (const float*)d_in[8],
        (const float*)d_in[9],  (const float*)d_in[10], (const float*)d_in[11],
        (const float*)d_in[12], (const float*)d_in[13],
        (float*)d_out);
}